// round 17
// baseline (speedup 1.0000x reference)
#include <cuda_runtime.h>
#include <cuda_fp16.h>
#include <cstdint>

// ============================================================================
//   x : (3, 8192) fp32   W1 : (8192, 64)   W2 : (64, 64)   W3 : (64, 1)
//   out = mean(per_row MLP(corr)) - regu2*sum(x2) - regu*sum(exp(x2/(2 rl^2)))
//   corr[i,j] = sum_c x[c,(i+j)%N] * x[c,i]
//
//   R17: 256 CTAs x 256 thr (2 independent CTAs/SM) to break warp convoys:
//   same 16 warps/SM but desynced halves, 8-warp chunk barriers. e4m3 B,
//   fp16 MMA, permuted coalesced epilogue (all from R16).
// ============================================================================
#define NTOK 8192
#define KEIGHTH 1024
#define NPAIRS 656                       // (1024 + 256 + 32)/2 fp16 pairs/channel
#define ODD_BASE 1968                    // 3*656; ≡16 mod 32 -> disjoint banks
#define NCTA 256u

// smem word offsets
#define OFF_BND   0
#define OFF_W2S   3936
#define OFF_Z1S   (3936 + 4096)          // 8032
#define OFF_BBUF  (8032 + 2048)          // 10080; 2 x 2048 words (8KB each)
#define OFF_W3S   (OFF_BBUF + 4096)      // 14176
#define OFF_WSUM  (OFF_W3S + 64)
#define OFF_RSUM  (OFF_WSUM + 16)
#define SMEM_WORDS (OFF_RSUM + 2)        // 14258 words = 57032 B

__device__ double g_acc[3];                                // sum_x2, sum_exp, sum_per_row
__device__ unsigned int g_done;
__device__ unsigned int g_bar;
__device__ __align__(16) uint32_t g_ph[8 * NTOK * 32];     // fp16 partials, permuted [ke][row][p]
__device__ __align__(16) uint32_t g_w1p8[512 * 4 * 32 * 2]; // e4m3 frags: uint2 per (ks,jpos,lane)

__device__ __forceinline__ uint32_t smem_u32(const void* p) {
    uint32_t a;
    asm("{ .reg .u64 t; cvta.to.shared.u64 t, %1; cvt.u32.u64 %0, t; }" : "=r"(a) : "l"(p));
    return a;
}
__device__ __forceinline__ void cpasync16(uint32_t dst, const void* src) {
    asm volatile("cp.async.ca.shared.global [%0], [%1], 16;" :: "r"(dst), "l"(src));
}
#define CPASYNC_COMMIT() asm volatile("cp.async.commit_group;" ::: "memory")
#define CPASYNC_WAIT1()  asm volatile("cp.async.wait_group 1;" ::: "memory")

__device__ __forceinline__ uint32_t pack_f16x2(float lo, float hi) {
    uint32_t r;
    asm("cvt.rn.f16x2.f32 %0, %1, %2;" : "=r"(r) : "f"(hi), "f"(lo));
    return r;
}
__device__ __forceinline__ uint16_t pack_e4m3x2(float lo, float hi) {
    uint16_t r;
    asm("cvt.rn.satfinite.e4m3x2.f32 %0, %1, %2;" : "=h"(r) : "f"(hi), "f"(lo));
    return r;
}
__device__ __forceinline__ void e4m3x4_to_2f16x2(uint32_t w, uint32_t& a, uint32_t& b) {
    asm("{\n\t.reg .b16 lo, hi;\n\t"
        "mov.b32 {lo, hi}, %2;\n\t"
        "cvt.rn.f16x2.e4m3x2 %0, lo;\n\t"
        "cvt.rn.f16x2.e4m3x2 %1, hi;\n\t}"
        : "=r"(a), "=r"(b) : "r"(w));
}
__device__ __forceinline__ uint32_t bcast_h2(float v) {
    const __half h = __float2half_rn(v);
    const __half2 h2 = __half2half2(h);
    return *reinterpret_cast<const uint32_t*>(&h2);
}
__device__ __forceinline__ uint32_t dot3h(uint32_t x0, uint32_t x1, uint32_t x2,
                                          uint32_t u, uint32_t v, uint32_t w) {
    const __half2 r = __hfma2(*(const __half2*)&x0, *(const __half2*)&u,
                      __hfma2(*(const __half2*)&x1, *(const __half2*)&v,
                      __hmul2(*(const __half2*)&x2, *(const __half2*)&w)));
    return *reinterpret_cast<const uint32_t*>(&r);
}
__device__ __forceinline__ float elu1(float v) { return v > 0.f ? v : expm1f(v); }

#define MMA_F16(d0,d1,a0,a1,a2,a3,b0,b1) \
    asm volatile("mma.sync.aligned.m16n8k16.row.col.f16.f16.f16.f16 " \
                 "{%0,%1}, {%2,%3,%4,%5}, {%6,%7}, {%0,%1};" \
                 : "+r"(d0), "+r"(d1) \
                 : "r"(a0), "r"(a1), "r"(a2), "r"(a3), "r"(b0), "r"(b1))

// Software grid barrier: 256 CTAs, 2/SM, all co-resident.
__device__ __forceinline__ void grid_bar(unsigned target) {
    __syncthreads();
    if (threadIdx.x == 0) {
        __threadfence();
        atomicAdd(&g_bar, 1u);
        while (*((volatile unsigned*)&g_bar) < target) {}
        __threadfence();
    }
    __syncthreads();
}

// ---------------------------------------------------------------------------
// Fused kernel. grid = 256 x 256 threads (8 warps, 32 rows/warp).
// ---------------------------------------------------------------------------
__global__ __launch_bounds__(256, 2) void fused_kernel(
        const float* __restrict__ x,  const float* __restrict__ W1,
        const float* __restrict__ W2, const float* __restrict__ W3,
        const float* __restrict__ regu2, const float* __restrict__ regu,
        const float* __restrict__ rl_p, float* __restrict__ out) {
    extern __shared__ float smem[];
    uint32_t* bnd = (uint32_t*)smem + OFF_BND;
    float* w2s  = smem + OFF_W2S;
    float* z1s  = smem + OFF_Z1S;
    const uint2* bsm = (const uint2*)(smem + OFF_BBUF);   // B double buffer (e4m3)
    float* w3s  = smem + OFF_W3S;
    float* wsum = smem + OFF_WSUM;
    float* rsum = smem + OFF_RSUM;

    const int tid = threadIdx.x, warp = tid >> 5, lane = tid & 31;
    const int g = lane >> 2, t = lane & 3;
    const int b = blockIdx.x;
    const int it = b >> 3, ke = b & 7;
    const int i0 = it * 256, jbase = ke * KEIGHTH;

    if (b == 0 && tid == 0) { g_acc[0] = 0.0; g_acc[1] = 0.0; g_acc[2] = 0.0; }

    // ---- Phase 0a: stage band as fp16 pairs (even + shifted-by-1 odd) ----
    for (int p = tid; p < NPAIRS; p += 256) {
        const int e0 = (i0 + jbase + 2 * p)     & (NTOK - 1);
        const int e1 = (i0 + jbase + 2 * p + 1) & (NTOK - 1);
        const int e2 = (i0 + jbase + 2 * p + 2) & (NTOK - 1);
        #pragma unroll
        for (int c = 0; c < 3; c++) {
            const float a = x[c * NTOK + e0];
            const float bb = x[c * NTOK + e1];
            const float cc = x[c * NTOK + e2];
            bnd[c * NPAIRS + p]            = pack_f16x2(a, bb);
            bnd[ODD_BASE + c * NPAIRS + p] = pack_f16x2(bb, cc);
        }
    }

    // ---- Phase 0b: W1 -> e4m3 fragments (x128), 2 k-steps per CTA ----
    {
        const float4* src = (const float4*)(W1 + b * 2048);   // 32 k-rows x 64
        float4* w4 = (float4*)w2s;
        w4[tid]       = src[tid];
        w4[tid + 256] = src[tid + 256];
        __syncthreads();
        const int ksl = tid >> 7, inner = tid & 127;           // ksl 0..1
        const int ln = inner >> 2, jpos = inner & 3;
        uint16_t e[4];
        #pragma unroll
        for (int j = 0; j < 4; j++) {
            const int q = jpos * 4 + j;
            const int nt = q >> 1, r = q & 1;
            const int k = ksl * 16 + (ln & 3) * 2 + r * 8;
            const int n = nt * 8 + (ln >> 2);
            e[j] = pack_e4m3x2(128.f * w2s[k * 64 + n], 128.f * w2s[(k + 1) * 64 + n]);
        }
        uint2 E;
        E.x = (uint32_t)e[0] | ((uint32_t)e[1] << 16);
        E.y = (uint32_t)e[2] | ((uint32_t)e[3] << 16);
        ((uint2*)g_w1p8)[(b * 2 + ksl) * 128 + jpos * 32 + ln] = E;
        __syncthreads();
    }

    // ---- Phase 0c: stage W2/W3; reg sums for this CTA's 32 tokens (warp 0) ----
    #pragma unroll
    for (int tv = tid; tv < 4096; tv += 256) w2s[tv] = W2[tv];
    if (tid < 64) w3s[tid] = W3[tid];
    if (warp == 0) {
        const int tok = b * 32 + lane;
        const float a = x[tok], bb = x[NTOK + tok], c = x[2 * NTOK + tok];
        float x2t = fmaf(a, a, fmaf(bb, bb, c * c));
        const float rl = rl_p[0];
        float et = expf(x2t / (2.f * rl * rl));
        #pragma unroll
        for (int o = 16; o > 0; o >>= 1) {
            x2t += __shfl_down_sync(0xFFFFFFFFu, x2t, o);
            et  += __shfl_down_sync(0xFFFFFFFFu, et, o);
        }
        if (lane == 0) { rsum[0] = x2t; rsum[1] = et; }
    }

    // row scalars: 4 positions (r0+8m), 3 channels, broadcast half2
    const int r0 = i0 + warp * 32 + g;
    uint32_t xs[4][3];
    #pragma unroll
    for (int m = 0; m < 4; m++) {
        xs[m][0] = bcast_h2(x[r0 + 8 * m]);
        xs[m][1] = bcast_h2(x[NTOK + r0 + 8 * m]);
        xs[m][2] = bcast_h2(x[2 * NTOK + r0 + 8 * m]);
    }

    // ---- grid barrier 1: all g_w1p8 fragments written ----
    grid_bar(NCTA);

    // ---- Phase 1: fp16 corr-build + fp16 MMA, e4m3 B via cp.async ----
    const int par = g & 1;
    const int ibp = (warp * 32 + g + 2 * t - par) >> 1;  // pair index
    const uint32_t* sb = bnd + (par ? ODD_BASE : 0);
    const uint32_t* p0 = sb + ibp;
    const uint32_t* p1 = sb + NPAIRS + ibp;
    const uint32_t* p2 = sb + 2 * NPAIRS + ibp;

    // cp.async staging: chunk = 8 k-steps = 1024 uint2 = 8KB
    const char* bgbase = (const char*)(g_w1p8) + (size_t)ke * 65536;   // 1KB per ks
    const uint32_t bs_addr = smem_u32(smem + OFF_BBUF);
    #pragma unroll
    for (int c = 0; c < 2; c++) {
        cpasync16(bs_addr + c * 8192 + tid * 16, bgbase + (size_t)c * 8192 + tid * 16);
        cpasync16(bs_addr + c * 8192 + tid * 16 + 4096,
                  bgbase + (size_t)c * 8192 + tid * 16 + 4096);
        CPASYNC_COMMIT();
    }

    uint32_t acc[2][8][2];
    #pragma unroll
    for (int s = 0; s < 2; s++)
        #pragma unroll
        for (int nt = 0; nt < 8; nt++) { acc[s][nt][0] = 0u; acc[s][nt][1] = 0u; }

    uint32_t u0 = p0[0], u1 = p0[4], u2 = p0[8];
    uint32_t v0 = p1[0], v1 = p1[4], v2 = p1[8];
    uint32_t w0 = p2[0], w1 = p2[4], w2 = p2[8];

    for (int c = 0; c < 8; c++) {
        CPASYNC_WAIT1();                 // chunk c resident (<=1 group pending)
        __syncthreads();

        const uint2* bc2 = bsm + (c & 1) * 1024 + lane;
        #pragma unroll
        for (int kk = 0; kk < 8; kk++) {
            const int ks = c * 8 + kk;
            const int e = ks * 8;
            const uint32_t u3 = p0[e + 12], u4 = p0[e + 16];
            const uint32_t v3 = p1[e + 12], v4 = p1[e + 16];
            const uint32_t w3 = p2[e + 12], w4 = p2[e + 16];

            const uint32_t a0 = dot3h(xs[0][0], xs[0][1], xs[0][2], u0, v0, w0);
            const uint32_t a2 = dot3h(xs[0][0], xs[0][1], xs[0][2], u1, v1, w1);
            const uint32_t a1 = dot3h(xs[1][0], xs[1][1], xs[1][2], u1, v1, w1);
            const uint32_t a3 = dot3h(xs[1][0], xs[1][1], xs[1][2], u2, v2, w2);
            const uint32_t c0f = dot3h(xs[2][0], xs[2][1], xs[2][2], u2, v2, w2);
            const uint32_t c2f = dot3h(xs[2][0], xs[2][1], xs[2][2], u3, v3, w3);
            const uint32_t c1f = dot3h(xs[3][0], xs[3][1], xs[3][2], u3, v3, w3);
            const uint32_t c3f = dot3h(xs[3][0], xs[3][1], xs[3][2], u4, v4, w4);

            const uint2 E0 = bc2[kk * 128];
            const uint2 E1 = bc2[kk * 128 + 32];
            const uint2 E2 = bc2[kk * 128 + 64];
            const uint2 E3 = bc2[kk * 128 + 96];
            uint32_t b00, b01, b02, b03, b10, b11, b12, b13;
            uint32_t b20, b21, b22, b23, b30, b31, b32, b33;
            e4m3x4_to_2f16x2(E0.x, b00, b01); e4m3x4_to_2f16x2(E0.y, b02, b03);
            e4m3x4_to_2f16x2(E1.x, b10, b11); e4m3x4_to_2f16x2(E1.y, b12, b13);
            e4m3x4_to_2f16x2(E2.x, b20, b21); e4m3x4_to_2f16x2(E2.y, b22, b23);
            e4m3x4_to_2f16x2(E3.x, b30, b31); e4m3x4_to_2f16x2(E3.y, b32, b33);

            MMA_F16(acc[0][0][0], acc[0][0][1], a0, a1, a2, a3, b00, b01);
            MMA_F16(acc[0][1][0], acc[0][1][1], a0, a1, a2, a3, b02, b03);
            MMA_F16(acc[0][2][0], acc[0][2][1], a0, a1, a2, a3, b10, b11);
            MMA_F16(acc[0][3][0], acc[0][3][1], a0, a1, a2, a3, b12, b13);
            MMA_F16(acc[0][4][0], acc[0][4][1], a0, a1, a2, a3, b20, b21);
            MMA_F16(acc[0][5][0], acc[0][5][1], a0, a1, a2, a3, b22, b23);
            MMA_F16(acc[0][6][0], acc[0][6][1], a0, a1, a2, a3, b30, b31);
            MMA_F16(acc[0][7][0], acc[0][7][1], a0, a1, a2, a3, b32, b33);

            MMA_F16(acc[1][0][0], acc[1][0][1], c0f, c1f, c2f, c3f, b00, b01);
            MMA_F16(acc[1][1][0], acc[1][1][1], c0f, c1f, c2f, c3f, b02, b03);
            MMA_F16(acc[1][2][0], acc[1][2][1], c0f, c1f, c2f, c3f, b10, b11);
            MMA_F16(acc[1][3][0], acc[1][3][1], c0f, c1f, c2f, c3f, b12, b13);
            MMA_F16(acc[1][4][0], acc[1][4][1], c0f, c1f, c2f, c3f, b20, b21);
            MMA_F16(acc[1][5][0], acc[1][5][1], c0f, c1f, c2f, c3f, b22, b23);
            MMA_F16(acc[1][6][0], acc[1][6][1], c0f, c1f, c2f, c3f, b30, b31);
            MMA_F16(acc[1][7][0], acc[1][7][1], c0f, c1f, c2f, c3f, b32, b33);

            u0 = u2; u1 = u3; u2 = u4;
            v0 = v2; v1 = v3; v2 = v4;
            w0 = w2; w1 = w3; w2 = w4;
        }

        __syncthreads();                 // all warps done with buf (c&1)
        if (c + 2 < 8) {
            cpasync16(bs_addr + (c & 1) * 8192 + tid * 16,
                      bgbase + (size_t)(c + 2) * 8192 + tid * 16);
            cpasync16(bs_addr + (c & 1) * 8192 + tid * 16 + 4096,
                      bgbase + (size_t)(c + 2) * 8192 + tid * 16 + 4096);
        }
        CPASYNC_COMMIT();
    }

    // epilogue: permuted layout [ke][row][p]; coalesced STG.128
    #pragma unroll
    for (int s = 0; s < 2; s++)
        #pragma unroll
        for (int d = 0; d < 2; d++) {
            const int row = r0 + 16 * s + 8 * d;
            uint32_t* basep = g_ph + ((size_t)(ke * NTOK + row) * 32) + t * 4;
            *(uint4*)(basep)      = make_uint4(acc[s][0][d], acc[s][1][d], acc[s][2][d], acc[s][3][d]);
            *(uint4*)(basep + 16) = make_uint4(acc[s][4][d], acc[s][5][d], acc[s][6][d], acc[s][7][d]);
        }

    // ---- grid barrier 2: all partials written ----
    grid_bar(2 * NCTA);

    // ---- Phase 2: MLP for this CTA's 32 rows (8 warps x 4 rows) ----
    const int cq = (lane & 16) | ((lane >> 2) & 3) | ((lane & 3) << 2);
    const int rbase = b * 32 + warp * 4;
    #pragma unroll
    for (int rr = 0; rr < 4; rr++) {
        float px = 0.f, py = 0.f;
        #pragma unroll
        for (int q = 0; q < 8; q++) {
            const uint32_t uu = g_ph[((size_t)q * NTOK + rbase + rr) * 32 + lane];
            const float2 p = __half22float2(*reinterpret_cast<const __half2*>(&uu));
            px += p.x; py += p.y;
        }
        px *= 0.0078125f;                // undo x128 W1 scale
        py *= 0.0078125f;
        z1s[(warp * 4 + rr) * 64 + 2 * cq]     = elu1(px);
        z1s[(warp * 4 + rr) * 64 + 2 * cq + 1] = elu1(py);
    }
    __syncwarp();

    float2 m[4];
    #pragma unroll
    for (int rr = 0; rr < 4; rr++) m[rr] = make_float2(0.f, 0.f);
    const float2* w2p = (const float2*)w2s + cq;
    const float* zw = z1s + warp * 4 * 64;
    #pragma unroll 8
    for (int f1 = 0; f1 < 64; f1++) {
        const float2 w = w2p[f1 * 32];
        #pragma unroll
        for (int rr = 0; rr < 4; rr++) {
            const float z = zw[rr * 64 + f1];
            m[rr].x = fmaf(z, w.x, m[rr].x);
            m[rr].y = fmaf(z, w.y, m[rr].y);
        }
    }

    const float w3a = w3s[2 * cq], w3b = w3s[2 * cq + 1];
    float tot = 0.f;
    #pragma unroll
    for (int rr = 0; rr < 4; rr++) {
        float s = fmaf(elu1(m[rr].x), w3a, elu1(m[rr].y) * w3b);
        #pragma unroll
        for (int o = 16; o > 0; o >>= 1) s += __shfl_down_sync(0xFFFFFFFFu, s, o);
        if (lane == 0) tot += elu1(s);
    }
    if (lane == 0) wsum[warp] = tot;
    __syncthreads();

    if (tid == 0) {
        float s = 0.f;
        #pragma unroll
        for (int wv = 0; wv < 8; wv++) s += wsum[wv];
        atomicAdd(&g_acc[2], (double)s);
        atomicAdd(&g_acc[0], (double)rsum[0]);
        atomicAdd(&g_acc[1], (double)rsum[1]);
        __threadfence();
        const unsigned int done = atomicAdd(&g_done, 1u);
        if (done == NCTA - 1u) {
            const double t0 = atomicAdd(&g_acc[0], 0.0);
            const double t1 = atomicAdd(&g_acc[1], 0.0);
            const double t2 = atomicAdd(&g_acc[2], 0.0);
            out[0] = (float)(t2 / (double)NTOK
                             - (double)regu2[0] * t0
                             - (double)regu[0] * t1);
            g_done = 0u;          // reset for next graph replay
            g_bar  = 0u;
        }
    }
}

// ---------------------------------------------------------------------------
// kernel_launch   d_in: 0=x 1=W1 2=W2 3=W3 4=regu2 5=regu 6=regu_length
// ---------------------------------------------------------------------------
extern "C" void kernel_launch(void* const* d_in, const int* in_sizes, int n_in,
                              void* d_out, int out_size) {
    const float* x  = (const float*)d_in[0];
    const float* W1 = (const float*)d_in[1];
    const float* W2 = (const float*)d_in[2];
    const float* W3 = (const float*)d_in[3];
    const float* r2 = (const float*)d_in[4];
    const float* r  = (const float*)d_in[5];
    const float* rl = (const float*)d_in[6];
    float* out = (float*)d_out;

    static const int smem_bytes = SMEM_WORDS * sizeof(float);   // 57032
    cudaFuncSetAttribute(fused_kernel, cudaFuncAttributeMaxDynamicSharedMemorySize, smem_bytes);

    fused_kernel<<<256, 256, smem_bytes>>>(x, W1, W2, W3, r2, r, rl, out);
}